// round 4
// baseline (speedup 1.0000x reference)
#include <cuda_runtime.h>
#include <math.h>

// Problem constants (fixed for this problem instance)
#define BB    32
#define TT    8192
#define DD    64
#define NTOK  (BB * TT)      // 262144
#define NGRP  (NTOK / 4)     // 65536 groups of 4 tokens, each handled by one warp

// ---------------------------------------------------------------------------
// Device-global scratch (allocation-free kernel_launch requirement)
// ---------------------------------------------------------------------------
// Per-vocab precomputed first-layer tables (biases folded into *current* rows):
//   T2a[i] = emb[i] @ mlp2_W1[  0: 64]           (applied to token t-1)
//   T2b[i] = emb[i] @ mlp2_W1[ 64:128] + mlp2_b1 (applied to token t)
//   T3a[i] = emb[i] @ mlp3_W1[  0: 64]           (t-2)
//   T3b[i] = emb[i] @ mlp3_W1[ 64:128]           (t-1)
//   T3c[i] = emb[i] @ mlp3_W1[128:192] + mlp3_b1 (t)
__device__ float g_T2a[500 * 256];
__device__ float g_T2b[500 * 256];
__device__ float g_T3a[500 * 256];
__device__ float g_T3b[500 * 256];
__device__ float g_T3c[500 * 256];
// gated value output [B, T, 64] — consumed by the conv kernel
__device__ float g_Val[(size_t)NTOK * 64];

__device__ __forceinline__ float silu_f(float x) {
    return __fdividef(x, 1.0f + __expf(-x));
}

__device__ __forceinline__ float wsum(float v) {
#pragma unroll
    for (int m = 16; m > 0; m >>= 1) v += __shfl_xor_sync(0xffffffffu, v, m);
    return v;
}

// ---------------------------------------------------------------------------
// Kernel 1: per-vocab table precompute.  500 blocks x 256 threads.
// ---------------------------------------------------------------------------
__global__ void precompute_tables(const float* __restrict__ emb,
                                  const float* __restrict__ W1_2,
                                  const float* __restrict__ b1_2,
                                  const float* __restrict__ W1_3,
                                  const float* __restrict__ b1_3) {
    __shared__ float e[64];
    const int id = blockIdx.x;
    const int o  = threadIdx.x;
    if (o < 64) e[o] = emb[id * 64 + o];
    __syncthreads();

    float a2 = 0.f, b2 = 0.f, a3 = 0.f, b3 = 0.f, c3 = 0.f;
#pragma unroll 8
    for (int d = 0; d < 64; d++) {
        const float ev = e[d];
        a2 += ev * W1_2[d * 256 + o];
        b2 += ev * W1_2[(64 + d) * 256 + o];
        a3 += ev * W1_3[d * 256 + o];
        b3 += ev * W1_3[(64 + d) * 256 + o];
        c3 += ev * W1_3[(128 + d) * 256 + o];
    }
    g_T2a[id * 256 + o] = a2;
    g_T2b[id * 256 + o] = b2 + b1_2[o];
    g_T3a[id * 256 + o] = a3;
    g_T3b[id * 256 + o] = b3;
    g_T3c[id * 256 + o] = c3 + b1_3[o];
}

// ---------------------------------------------------------------------------
// Kernel 2: main fused kernel.  512 threads (16 warps), warp = 4 tokens.
// Dynamic smem layout (floats):
//   [    0 : 16384)  W2_2 staged (256x64)
//   [16384 : 32768)  W2_3 staged (256x64)
//   [32768 : 49152)  per-warp h buffer   (16 warps x 4 tok x 256)
//   [49152 : 57344)  per-warp emb buffer (16 warps x 4 tok x 128)
// Total 57344 floats = 229376 bytes.
// ---------------------------------------------------------------------------
__global__ void __launch_bounds__(512, 1)
main_kernel(const int*   __restrict__ ids_g,
            const float* __restrict__ hidden,
            const float* __restrict__ W2_2g, const float* __restrict__ b2_2,
            const float* __restrict__ W2_3g, const float* __restrict__ b2_3,
            const float* __restrict__ keyW,  const float* __restrict__ keyb,
            const float* __restrict__ valW,  const float* __restrict__ valb,
            const float* __restrict__ n1g,   const float* __restrict__ n1b,
            const float* __restrict__ n2g,   const float* __restrict__ n2b) {
    extern __shared__ float sm[];
    float* W2as = sm;
    float* W2bs = sm + 16384;
    const int tid  = threadIdx.x;
    const int wid  = tid >> 5;
    const int lane = tid & 31;
    float* hb = sm + 32768 + wid * 1024;  // 4 x 256
    float* eb = sm + 49152 + wid * 512;   // 4 x 128

    for (int i = tid; i < 16384; i += 512) {
        W2as[i] = W2_2g[i];
        W2bs[i] = W2_3g[i];
    }
    __syncthreads();

    // Hoisted per-lane constants
    const float bb20 = b2_2[lane], bb21 = b2_2[lane + 32];
    const float bb30 = b2_3[lane], bb31 = b2_3[lane + 32];
    const float kb0  = keyb[lane], kb1  = keyb[lane + 32];
    const float vb0  = valb[lane], vb1  = valb[lane + 32];
    const float g1x  = n1g[lane],  g1y  = n1g[lane + 32];
    const float o1x  = n1b[lane],  o1y  = n1b[lane + 32];
    const float g2x  = n2g[lane],  g2y  = n2g[lane + 32];
    const float o2x  = n2b[lane],  o2y  = n2b[lane + 32];

    const int o0 = lane * 8;

    for (int grp = blockIdx.x * 16 + wid; grp < NGRP; grp += gridDim.x * 16) {
        const int t0 = grp * 4;
        const int b  = t0 >> 13;      // / 8192
        const int p0 = t0 & 8191;

        // guard against overwriting hb/eb while previous iteration's lanes read
        __syncwarp();

        int idx[6];  // token ids at positions p0-2 .. p0+3 (-1 = padded)
#pragma unroll
        for (int j = 0; j < 6; j++) {
            const int pp = p0 + j - 2;
            idx[j] = (pp >= 0) ? ids_g[b * TT + pp] : -1;
        }

        // ---------------- h2 build ----------------
#pragma unroll
        for (int tok = 0; tok < 4; tok++) {
            const float* rc = g_T2b + idx[tok + 2] * 256 + o0;
            float4 x0 = *(const float4*)(rc);
            float4 x1 = *(const float4*)(rc + 4);
            const int ip = idx[tok + 1];
            if (ip >= 0) {
                const float* rp = g_T2a + ip * 256 + o0;
                const float4 y0 = *(const float4*)(rp);
                const float4 y1 = *(const float4*)(rp + 4);
                x0.x += y0.x; x0.y += y0.y; x0.z += y0.z; x0.w += y0.w;
                x1.x += y1.x; x1.y += y1.y; x1.z += y1.z; x1.w += y1.w;
            }
            x0.x = silu_f(x0.x); x0.y = silu_f(x0.y); x0.z = silu_f(x0.z); x0.w = silu_f(x0.w);
            x1.x = silu_f(x1.x); x1.y = silu_f(x1.y); x1.z = silu_f(x1.z); x1.w = silu_f(x1.w);
            *(float4*)(hb + tok * 256 + o0)     = x0;
            *(float4*)(hb + tok * 256 + o0 + 4) = x1;
        }
        __syncwarp();

        // ---------------- out2 = h2 @ W2_2 ----------------
        float a0[4], a1[4];
#pragma unroll
        for (int t = 0; t < 4; t++) { a0[t] = 0.f; a1[t] = 0.f; }
#pragma unroll 2
        for (int k = 0; k < 256; k += 4) {
            const float4 h0 = *(const float4*)(hb + 0 * 256 + k);
            const float4 h1 = *(const float4*)(hb + 1 * 256 + k);
            const float4 h2 = *(const float4*)(hb + 2 * 256 + k);
            const float4 h3 = *(const float4*)(hb + 3 * 256 + k);
#pragma unroll
            for (int u = 0; u < 4; u++) {
                const float w0 = W2as[(k + u) * 64 + lane];
                const float w1 = W2as[(k + u) * 64 + lane + 32];
                const float c0 = ((const float*)&h0)[u];
                const float c1 = ((const float*)&h1)[u];
                const float c2 = ((const float*)&h2)[u];
                const float c3 = ((const float*)&h3)[u];
                a0[0] += c0 * w0; a1[0] += c0 * w1;
                a0[1] += c1 * w0; a1[1] += c1 * w1;
                a0[2] += c2 * w0; a1[2] += c2 * w1;
                a0[3] += c3 * w0; a1[3] += c3 * w1;
            }
        }
        __syncwarp();
#pragma unroll
        for (int t = 0; t < 4; t++) {
            eb[t * 128 + lane]      = a0[t] + bb20;
            eb[t * 128 + lane + 32] = a1[t] + bb21;
        }

        // ---------------- h3 build (reuse hb) ----------------
#pragma unroll
        for (int tok = 0; tok < 4; tok++) {
            const float* rc = g_T3c + idx[tok + 2] * 256 + o0;
            float4 x0 = *(const float4*)(rc);
            float4 x1 = *(const float4*)(rc + 4);
            const int i1 = idx[tok + 1];
            if (i1 >= 0) {
                const float* rp = g_T3b + i1 * 256 + o0;
                const float4 y0 = *(const float4*)(rp);
                const float4 y1 = *(const float4*)(rp + 4);
                x0.x += y0.x; x0.y += y0.y; x0.z += y0.z; x0.w += y0.w;
                x1.x += y1.x; x1.y += y1.y; x1.z += y1.z; x1.w += y1.w;
            }
            const int i2 = idx[tok];
            if (i2 >= 0) {
                const float* rp = g_T3a + i2 * 256 + o0;
                const float4 y0 = *(const float4*)(rp);
                const float4 y1 = *(const float4*)(rp + 4);
                x0.x += y0.x; x0.y += y0.y; x0.z += y0.z; x0.w += y0.w;
                x1.x += y1.x; x1.y += y1.y; x1.z += y1.z; x1.w += y1.w;
            }
            x0.x = silu_f(x0.x); x0.y = silu_f(x0.y); x0.z = silu_f(x0.z); x0.w = silu_f(x0.w);
            x1.x = silu_f(x1.x); x1.y = silu_f(x1.y); x1.z = silu_f(x1.z); x1.w = silu_f(x1.w);
            *(float4*)(hb + tok * 256 + o0)     = x0;
            *(float4*)(hb + tok * 256 + o0 + 4) = x1;
        }
        __syncwarp();

        // ---------------- out3 = h3 @ W2_3 ----------------
#pragma unroll
        for (int t = 0; t < 4; t++) { a0[t] = 0.f; a1[t] = 0.f; }
#pragma unroll 2
        for (int k = 0; k < 256; k += 4) {
            const float4 h0 = *(const float4*)(hb + 0 * 256 + k);
            const float4 h1 = *(const float4*)(hb + 1 * 256 + k);
            const float4 h2 = *(const float4*)(hb + 2 * 256 + k);
            const float4 h3 = *(const float4*)(hb + 3 * 256 + k);
#pragma unroll
            for (int u = 0; u < 4; u++) {
                const float w0 = W2bs[(k + u) * 64 + lane];
                const float w1 = W2bs[(k + u) * 64 + lane + 32];
                const float c0 = ((const float*)&h0)[u];
                const float c1 = ((const float*)&h1)[u];
                const float c2 = ((const float*)&h2)[u];
                const float c3 = ((const float*)&h3)[u];
                a0[0] += c0 * w0; a1[0] += c0 * w1;
                a0[1] += c1 * w0; a1[1] += c1 * w1;
                a0[2] += c2 * w0; a1[2] += c2 * w1;
                a0[3] += c3 * w0; a1[3] += c3 * w1;
            }
        }
#pragma unroll
        for (int t = 0; t < 4; t++) {
            eb[t * 128 + 64 + lane]      = a0[t] + bb30;
            eb[t * 128 + 96 + lane]      = a1[t] + bb31;
        }
        __syncwarp();

        // ---------------- k / v = emb @ [keyW | valW] ----------------
        float ka0[4], ka1[4], va0[4], va1[4];
#pragma unroll
        for (int t = 0; t < 4; t++) { ka0[t] = ka1[t] = va0[t] = va1[t] = 0.f; }
        for (int i = 0; i < 128; i += 4) {
            const float4 e0 = *(const float4*)(eb + 0 * 128 + i);
            const float4 e1 = *(const float4*)(eb + 1 * 128 + i);
            const float4 e2 = *(const float4*)(eb + 2 * 128 + i);
            const float4 e3 = *(const float4*)(eb + 3 * 128 + i);
#pragma unroll
            for (int u = 0; u < 4; u++) {
                const int r = (i + u) * 64;
                const float kw0 = keyW[r + lane];
                const float kw1 = keyW[r + lane + 32];
                const float vw0 = valW[r + lane];
                const float vw1 = valW[r + lane + 32];
                const float c0 = ((const float*)&e0)[u];
                const float c1 = ((const float*)&e1)[u];
                const float c2 = ((const float*)&e2)[u];
                const float c3 = ((const float*)&e3)[u];
                ka0[0] += c0 * kw0; ka1[0] += c0 * kw1; va0[0] += c0 * vw0; va1[0] += c0 * vw1;
                ka0[1] += c1 * kw0; ka1[1] += c1 * kw1; va0[1] += c1 * vw0; va1[1] += c1 * vw1;
                ka0[2] += c2 * kw0; ka1[2] += c2 * kw1; va0[2] += c2 * vw0; va1[2] += c2 * vw1;
                ka0[3] += c3 * kw0; ka1[3] += c3 * kw1; va0[3] += c3 * vw0; va1[3] += c3 * vw1;
            }
        }

        // ---------------- LN(k), LN(hidden), gate, value ----------------
#pragma unroll
        for (int tok = 0; tok < 4; tok++) {
            const float kd0 = ka0[tok] + kb0;
            const float kd1 = ka1[tok] + kb1;
            const float vd0 = va0[tok] + vb0;
            const float vd1 = va1[tok] + vb1;

            const float mk = wsum(kd0 + kd1) * (1.0f / 64.0f);
            const float qk = wsum(kd0 * kd0 + kd1 * kd1) * (1.0f / 64.0f);
            const float ik = rsqrtf(qk - mk * mk + 1e-5f);
            const float nk0 = (kd0 - mk) * ik * g1x + o1x;
            const float nk1 = (kd1 - mk) * ik * g1y + o1y;

            const float* hr = hidden + ((size_t)(t0 + tok)) * 64;
            const float hq0 = hr[lane];
            const float hq1 = hr[lane + 32];
            const float mh = wsum(hq0 + hq1) * (1.0f / 64.0f);
            const float qh = wsum(hq0 * hq0 + hq1 * hq1) * (1.0f / 64.0f);
            const float ih = rsqrtf(qh - mh * mh + 1e-5f);
            const float nq0 = (hq0 - mh) * ih * g2x + o2x;
            const float nq1 = (hq1 - mh) * ih * g2y + o2y;

            const float dp = wsum(nk0 * nq0 + nk1 * nq1) * 0.125f;  // / sqrt(64)
            const float sq = sqrtf(fmaxf(fabsf(dp), 1e-6f));
            const float gs = (dp > 0.f) ? sq : ((dp < 0.f) ? -sq : 0.f);
            const float gate = __fdividef(1.0f, 1.0f + __expf(-gs));

            float* vout = g_Val + ((size_t)(t0 + tok)) * 64;
            vout[lane]      = gate * vd0;
            vout[lane + 32] = gate * vd1;
        }
    }
}

// ---------------------------------------------------------------------------
// Kernel 3: causal dilated depthwise conv over LN(value) + residual.
// Warp per token; y[t,d] = sum_{j=0..3} w[d,j] * LN(V)[t-9+3j, d], zeros for t'<0.
// out = V[t] + silu(y)
// ---------------------------------------------------------------------------
__global__ void conv_kernel(const float* __restrict__ cw,
                            const float* __restrict__ cg,
                            const float* __restrict__ cb,
                            float* __restrict__ out) {
    const int gw   = (blockIdx.x * blockDim.x + threadIdx.x) >> 5;
    const int lane = threadIdx.x & 31;
    if (gw >= NTOK) return;
    const int b  = gw >> 13;
    const int p  = gw & 8191;
    const int d0 = lane * 2;

    const float4 w0 = *(const float4*)(cw + d0 * 4);      // taps for d0
    const float4 w1 = *(const float4*)(cw + d0 * 4 + 4);  // taps for d0+1
    const float cg0 = cg[d0], cg1 = cg[d0 + 1];
    const float cb0 = cb[d0], cb1 = cb[d0 + 1];

    float y0 = 0.f, y1 = 0.f;
    float v0c = 0.f, v1c = 0.f;
    const float* base = g_Val + ((size_t)b * TT) * 64;

#pragma unroll
    for (int j = 0; j < 4; j++) {
        const int tp = p - 9 + 3 * j;
        if (tp >= 0) {
            const float2 v = *(const float2*)(base + (size_t)tp * 64 + d0);
            const float m   = wsum(v.x + v.y) * (1.0f / 64.0f);
            const float q   = wsum(v.x * v.x + v.y * v.y) * (1.0f / 64.0f);
            const float inv = rsqrtf(q - m * m + 1e-5f);
            const float n0  = (v.x - m) * inv * cg0 + cb0;
            const float n1  = (v.y - m) * inv * cg1 + cb1;
            y0 += ((const float*)&w0)[j] * n0;
            y1 += ((const float*)&w1)[j] * n1;
            if (j == 3) { v0c = v.x; v1c = v.y; }
        }
    }

    const float2 res = make_float2(v0c + silu_f(y0), v1c + silu_f(y1));
    *(float2*)(out + (size_t)gw * 64 + d0) = res;
}

// ---------------------------------------------------------------------------
// Host launcher
// ---------------------------------------------------------------------------
extern "C" void kernel_launch(void* const* d_in, const int* in_sizes, int n_in,
                              void* d_out, int out_size) {
    const float* hidden = (const float*)d_in[0];
    const int*   ids    = (const int*)d_in[1];
    const float* emb    = (const float*)d_in[2];
    const float* W1_2   = (const float*)d_in[3];
    const float* b1_2   = (const float*)d_in[4];
    const float* W2_2   = (const float*)d_in[5];
    const float* b2_2   = (const float*)d_in[6];
    const float* W1_3   = (const float*)d_in[7];
    const float* b1_3   = (const float*)d_in[8];
    const float* W2_3   = (const float*)d_in[9];
    const float* b2_3   = (const float*)d_in[10];
    const float* keyW   = (const float*)d_in[11];
    const float* keyb   = (const float*)d_in[12];
    const float* valW   = (const float*)d_in[13];
    const float* valb   = (const float*)d_in[14];
    const float* n1g    = (const float*)d_in[15];
    const float* n1b    = (const float*)d_in[16];
    const float* n2g    = (const float*)d_in[17];
    const float* n2b    = (const float*)d_in[18];
    const float* cw     = (const float*)d_in[19];
    const float* cg     = (const float*)d_in[20];
    const float* cb     = (const float*)d_in[21];
    float* out = (float*)d_out;

    precompute_tables<<<500, 256>>>(emb, W1_2, b1_2, W1_3, b1_3);

    const size_t smem = 57344 * sizeof(float);  // 229376 B
    cudaFuncSetAttribute(main_kernel, cudaFuncAttributeMaxDynamicSharedMemorySize,
                         (int)smem);
    main_kernel<<<1024, 512, smem>>>(ids, hidden, W2_2, b2_2, W2_3, b2_3,
                                     keyW, keyb, valW, valb,
                                     n1g, n1b, n2g, n2b);

    conv_kernel<<<NTOK / 8, 256>>>(cw, cg, cb, out);
}